// round 7
// baseline (speedup 1.0000x reference)
#include <cuda_runtime.h>
#include <cstdint>

// Problem constants (shapes fixed by setup_inputs)
#define NC   19
#define HW   (512 * 1024)          // 524288
#define NB   16
#define NPIX (NB * HW)             // 8388608
#define HW4  (HW / 4)              // 131072 = 2^17
#define NP4  (NPIX / 4)            // 2097152
#define BINS (NC * NC)             // 361
#define WEIGHT 0.5
#define SMOOTH 1e-6
#define GRID 592                   // 148 SMs * 4 blocks -> exactly 1 wave
#define TPB  256

// Global scratch (zero-initialized; each launch leaves it zeroed again)
__device__ unsigned int g_cm[BINS];
__device__ unsigned int g_done;

// logits float4-index for pixel-group i4 (batch = i4>>17 since HW4=2^17):
// b*NC*HW4 + (i4 & (HW4-1)) == i4 + b*(NC-1)*HW4
__device__ __forceinline__ size_t lidx(int i4) {
    return (size_t)i4 + (size_t)(i4 >> 17) * ((NC - 1) * HW4);
}

__global__ __launch_bounds__(TPB)
void sensspec_fused_kernel(const float* __restrict__ logits,
                           const int* __restrict__ target,
                           float* __restrict__ out) {
    __shared__ unsigned int sh[BINS];
    for (int i = threadIdx.x; i < BINS; i += TPB) sh[i] = 0u;
    __syncthreads();

    const float4* L = reinterpret_cast<const float4*>(logits);
    const int4*   T = reinterpret_cast<const int4*>(target);

    // ---- phase 1: adjacent-pair argmax + block-local histogram ----
    // Thread handles groups (pg, pg+1): warp reads 1KB contiguous per class.
    // pg is even, batch boundaries are at multiples of HW4 (even>0), and
    // pg+1 crossing would need pg odd -> pair always within one batch.
    const int stride = GRID * TPB * 2;
    for (int pg = (blockIdx.x * TPB + threadIdx.x) * 2; pg < NP4; pg += stride) {
        const float4* p = L + lidx(pg);

        float4 m0 = __ldcs(p);
        float4 m1 = __ldcs(p + 1);
        int i0x = 0, i0y = 0, i0z = 0, i0w = 0;
        int i1x = 0, i1y = 0, i1z = 0, i1w = 0;
        #pragma unroll
        for (int c = 1; c < NC; c++) {
            const float4* q = p + (size_t)c * HW4;
            float4 v0 = __ldcs(q);
            float4 v1 = __ldcs(q + 1);
            if (v0.x > m0.x) { m0.x = v0.x; i0x = c; }
            if (v0.y > m0.y) { m0.y = v0.y; i0y = c; }
            if (v0.z > m0.z) { m0.z = v0.z; i0z = c; }
            if (v0.w > m0.w) { m0.w = v0.w; i0w = c; }
            if (v1.x > m1.x) { m1.x = v1.x; i1x = c; }
            if (v1.y > m1.y) { m1.y = v1.y; i1y = c; }
            if (v1.z > m1.z) { m1.z = v1.z; i1z = c; }
            if (v1.w > m1.w) { m1.w = v1.w; i1w = c; }
        }

        // target is int32 (JAX x64 disabled => int64 request yields int32)
        int4 t0 = __ldcs(T + pg);
        int4 t1 = __ldcs(T + pg + 1);

        atomicAdd(&sh[t0.x * NC + i0x], 1u);
        atomicAdd(&sh[t0.y * NC + i0y], 1u);
        atomicAdd(&sh[t0.z * NC + i0z], 1u);
        atomicAdd(&sh[t0.w * NC + i0w], 1u);
        atomicAdd(&sh[t1.x * NC + i1x], 1u);
        atomicAdd(&sh[t1.y * NC + i1y], 1u);
        atomicAdd(&sh[t1.z * NC + i1z], 1u);
        atomicAdd(&sh[t1.w * NC + i1w], 1u);
    }

    __syncthreads();
    for (int i = threadIdx.x; i < BINS; i += TPB) {
        unsigned int v = sh[i];
        if (v) atomicAdd(&g_cm[i], v);
    }

    // ---- phase 2: last block finalizes ----
    __threadfence();
    __shared__ bool is_last;
    if (threadIdx.x == 0) {
        unsigned int n = atomicAdd(&g_done, 1u);
        is_last = (n == GRID - 1);
    }
    __syncthreads();
    if (!is_last) return;

    __threadfence();  // ensure all blocks' g_cm atomics are visible

    if (threadIdx.x < 32) {
        int lane = threadIdx.x;
        double acc = 0.0;
        if (lane < NC) {
            double rowsum = 0.0, colsum = 0.0;
            #pragma unroll
            for (int j = 0; j < NC; j++) {
                rowsum += (double)g_cm[lane * NC + j];   // axis=1 (pred)
                colsum += (double)g_cm[j * NC + lane];   // axis=0 (true)
            }
            double tp = (double)g_cm[lane * NC + lane];
            double fp = rowsum - tp;
            double fn = colsum - tp;
            double tn = (double)NPIX - tp - fp - fn;     // sum(CM) is exact
            double sens = (tp + SMOOTH) / (tp + fn + SMOOTH);
            double spec = (tn + SMOOTH) / (tn + fp + SMOOTH);
            acc = WEIGHT * sens + (1.0 - WEIGHT) * spec;
        }
        #pragma unroll
        for (int off = 16; off > 0; off >>= 1)
            acc += __shfl_down_sync(0xFFFFFFFFu, acc, off);
        if (lane == 0)
            out[0] = (float)(1.0 - acc / (double)NC);
    }
    __syncthreads();

    // reset globals so the next graph replay starts clean (deterministic)
    for (int i = threadIdx.x; i < BINS; i += TPB) g_cm[i] = 0u;
    if (threadIdx.x == 0) g_done = 0u;
}

extern "C" void kernel_launch(void* const* d_in, const int* in_sizes, int n_in,
                              void* d_out, int out_size) {
    const float* logits = (const float*)d_in[0];
    const int*   target = (const int*)d_in[1];
    float* out = (float*)d_out;

    sensspec_fused_kernel<<<GRID, TPB>>>(logits, target, out);
}

// round 8
// speedup vs baseline: 1.2312x; 1.2312x over previous
#include <cuda_runtime.h>
#include <cstdint>

// Problem constants (shapes fixed by setup_inputs)
#define NC   19
#define HW   (512 * 1024)          // 524288
#define NB   16
#define NPIX (NB * HW)             // 8388608
#define HW4  (HW / 4)              // 131072 = 2^17
#define NP4  (NPIX / 4)            // 2097152
#define BINS (NC * NC)             // 361
#define WEIGHT 0.5
#define SMOOTH 1e-6
#define GRID 592                   // 148 SMs * 4 resident blocks -> 1 wave
#define TPB  256

// Global scratch (zero-initialized; each launch leaves it zeroed again)
__device__ unsigned int g_cm[BINS];
__device__ unsigned int g_done;

// logits float4-index for pixel-group i4 (batch = i4>>17 since HW4=2^17):
// b*NC*HW4 + (i4 & (HW4-1)) == i4 + b*(NC-1)*HW4
__device__ __forceinline__ size_t lidx(int i4) {
    return (size_t)i4 + (size_t)(i4 >> 17) * ((NC - 1) * HW4);
}

__global__ __launch_bounds__(TPB)
void sensspec_fused_kernel(const float* __restrict__ logits,
                           const int* __restrict__ target,
                           float* __restrict__ out) {
    __shared__ unsigned int sh[BINS];
    for (int i = threadIdx.x; i < BINS; i += TPB) sh[i] = 0u;
    __syncthreads();

    const float4* L = reinterpret_cast<const float4*>(logits);
    const int4*   T = reinterpret_cast<const int4*>(target);

    // ---- phase 1: argmax + block-local histogram (lane-stride-1) ----
    const int stride = GRID * TPB;
    for (int i4 = blockIdx.x * TPB + threadIdx.x; i4 < NP4; i4 += stride) {
        const float4* p = L + lidx(i4);

        // target is int32 (JAX x64 disabled => int64 request yields int32);
        // issue it first so it rides along with the class-load burst.
        int4 t = __ldcs(T + i4);

        float4 m = __ldcs(p);
        int ix = 0, iy = 0, iz = 0, iw = 0;
        #pragma unroll
        for (int c = 1; c < NC; c++) {
            float4 v = __ldcs(p + (size_t)c * HW4);
            if (v.x > m.x) { m.x = v.x; ix = c; }
            if (v.y > m.y) { m.y = v.y; iy = c; }
            if (v.z > m.z) { m.z = v.z; iz = c; }
            if (v.w > m.w) { m.w = v.w; iw = c; }
        }

        atomicAdd(&sh[t.x * NC + ix], 1u);
        atomicAdd(&sh[t.y * NC + iy], 1u);
        atomicAdd(&sh[t.z * NC + iz], 1u);
        atomicAdd(&sh[t.w * NC + iw], 1u);
    }

    __syncthreads();
    for (int i = threadIdx.x; i < BINS; i += TPB)
        atomicAdd(&g_cm[i], sh[i]);

    // ---- phase 2: last block finalizes ----
    __threadfence();
    __shared__ bool is_last;
    if (threadIdx.x == 0) {
        unsigned int n = atomicAdd(&g_done, 1u);
        is_last = (n == GRID - 1);
    }
    __syncthreads();
    if (!is_last) return;

    __threadfence();  // ensure all blocks' g_cm atomics are visible

    if (threadIdx.x < 32) {
        int lane = threadIdx.x;
        double acc = 0.0;
        if (lane < NC) {
            double rowsum = 0.0, colsum = 0.0;
            #pragma unroll
            for (int j = 0; j < NC; j++) {
                rowsum += (double)g_cm[lane * NC + j];   // axis=1 (pred)
                colsum += (double)g_cm[j * NC + lane];   // axis=0 (true)
            }
            double tp = (double)g_cm[lane * NC + lane];
            double fp = rowsum - tp;
            double fn = colsum - tp;
            double tn = (double)NPIX - tp - fp - fn;     // sum(CM) is exact
            double sens = (tp + SMOOTH) / (tp + fn + SMOOTH);
            double spec = (tn + SMOOTH) / (tn + fp + SMOOTH);
            acc = WEIGHT * sens + (1.0 - WEIGHT) * spec;
        }
        #pragma unroll
        for (int off = 16; off > 0; off >>= 1)
            acc += __shfl_down_sync(0xFFFFFFFFu, acc, off);
        if (lane == 0)
            out[0] = (float)(1.0 - acc / (double)NC);
    }
    __syncthreads();

    // reset globals so the next graph replay starts clean (deterministic)
    for (int i = threadIdx.x; i < BINS; i += TPB) g_cm[i] = 0u;
    if (threadIdx.x == 0) g_done = 0u;
}

extern "C" void kernel_launch(void* const* d_in, const int* in_sizes, int n_in,
                              void* d_out, int out_size) {
    const float* logits = (const float*)d_in[0];
    const int*   target = (const int*)d_in[1];
    float* out = (float*)d_out;

    sensspec_fused_kernel<<<GRID, TPB>>>(logits, target, out);
}

// round 9
// speedup vs baseline: 1.3299x; 1.0802x over previous
#include <cuda_runtime.h>
#include <cstdint>

// Problem constants (shapes fixed by setup_inputs)
#define NC   19
#define HW   (512 * 1024)          // 524288
#define NB   16
#define NPIX (NB * HW)             // 8388608
#define HW4  (HW / 4)              // 131072 = 2^17
#define NP4  (NPIX / 4)            // 2097152
#define BINS (NC * NC)             // 361
#define WEIGHT 0.5
#define SMOOTH 1e-6
#define GRID 1184
#define TPB  256

// Global scratch (zero-initialized; each launch leaves it zeroed again)
__device__ unsigned int g_cm[BINS];
__device__ unsigned int g_done;

__global__ __launch_bounds__(TPB, 4)
void sensspec_fused_kernel(const float* __restrict__ logits,
                           const int* __restrict__ target,
                           float* __restrict__ out) {
    __shared__ unsigned int sh[BINS];
    for (int i = threadIdx.x; i < BINS; i += TPB) sh[i] = 0u;
    __syncthreads();

    // ---- phase 1: argmax + block-local histogram (R3 structure) ----
    const int stride = GRID * TPB;
    for (int i4 = blockIdx.x * TPB + threadIdx.x; i4 < NP4; i4 += stride) {
        int b   = i4 >> 17;            // batch (HW4 = 2^17)
        int rem = i4 - (b << 17);
        const float4* base =
            reinterpret_cast<const float4*>(logits + (size_t)b * NC * HW) + rem;

        float4 m = __ldcs(base);
        int ix = 0, iy = 0, iz = 0, iw = 0;
        #pragma unroll
        for (int c = 1; c < NC; c++) {
            float4 v = __ldcs(base + (size_t)c * HW4);
            if (v.x > m.x) { m.x = v.x; ix = c; }
            if (v.y > m.y) { m.y = v.y; iy = c; }
            if (v.z > m.z) { m.z = v.z; iz = c; }
            if (v.w > m.w) { m.w = v.w; iw = c; }
        }

        // target is int32 (JAX x64 disabled => int64 request yields int32)
        int4 t = __ldcs(reinterpret_cast<const int4*>(target) + i4);

        atomicAdd(&sh[t.x * NC + ix], 1u);
        atomicAdd(&sh[t.y * NC + iy], 1u);
        atomicAdd(&sh[t.z * NC + iz], 1u);
        atomicAdd(&sh[t.w * NC + iw], 1u);
    }

    __syncthreads();
    for (int i = threadIdx.x; i < BINS; i += TPB) {
        unsigned int v = sh[i];
        if (v) atomicAdd(&g_cm[i], v);
    }

    // ---- phase 2: last block finalizes ----
    __threadfence();
    __shared__ bool is_last;
    if (threadIdx.x == 0) {
        unsigned int n = atomicAdd(&g_done, 1u);
        is_last = (n == GRID - 1);
    }
    __syncthreads();
    if (!is_last) return;

    __threadfence();  // ensure all blocks' g_cm atomics are visible

    if (threadIdx.x < 32) {
        int lane = threadIdx.x;
        double acc = 0.0;
        if (lane < NC) {
            double rowsum = 0.0, colsum = 0.0;
            #pragma unroll
            for (int j = 0; j < NC; j++) {
                rowsum += (double)g_cm[lane * NC + j];   // axis=1 (pred)
                colsum += (double)g_cm[j * NC + lane];   // axis=0 (true)
            }
            double tp = (double)g_cm[lane * NC + lane];
            double fp = rowsum - tp;
            double fn = colsum - tp;
            double tn = (double)NPIX - tp - fp - fn;     // sum(CM) is exact
            double sens = (tp + SMOOTH) / (tp + fn + SMOOTH);
            double spec = (tn + SMOOTH) / (tn + fp + SMOOTH);
            acc = WEIGHT * sens + (1.0 - WEIGHT) * spec;
        }
        #pragma unroll
        for (int off = 16; off > 0; off >>= 1)
            acc += __shfl_down_sync(0xFFFFFFFFu, acc, off);
        if (lane == 0)
            out[0] = (float)(1.0 - acc / (double)NC);
    }
    __syncthreads();

    // reset globals so the next graph replay starts clean (deterministic)
    for (int i = threadIdx.x; i < BINS; i += TPB) g_cm[i] = 0u;
    if (threadIdx.x == 0) g_done = 0u;
}

extern "C" void kernel_launch(void* const* d_in, const int* in_sizes, int n_in,
                              void* d_out, int out_size) {
    const float* logits = (const float*)d_in[0];
    const int*   target = (const int*)d_in[1];
    float* out = (float*)d_out;

    sensspec_fused_kernel<<<GRID, TPB>>>(logits, target, out);
}

// round 10
// speedup vs baseline: 1.3510x; 1.0159x over previous
#include <cuda_runtime.h>
#include <cstdint>

// Problem constants (shapes fixed by setup_inputs)
#define NC   19
#define HW   (512 * 1024)          // 524288
#define NB   16
#define NPIX (NB * HW)             // 8388608
#define HW4  (HW / 4)              // 131072 = 2^17
#define NP4  (NPIX / 4)            // 2097152
#define BINS (NC * NC)             // 361
#define WEIGHT 0.5
#define SMOOTH 1e-6
#define GRID 592                   // 148 SMs * 4 resident blocks = 1 full wave
#define TPB  256

// Global scratch (zero-initialized; each launch leaves it zeroed again)
__device__ unsigned int g_cm[BINS];
__device__ unsigned int g_done;

__global__ __launch_bounds__(TPB, 4)   // pins regs <= 64 -> 4 blocks/SM guaranteed
void sensspec_fused_kernel(const float* __restrict__ logits,
                           const int* __restrict__ target,
                           float* __restrict__ out) {
    __shared__ unsigned int sh[BINS];
    for (int i = threadIdx.x; i < BINS; i += TPB) sh[i] = 0u;
    __syncthreads();

    // ---- phase 1: argmax + block-local histogram (ceiling pattern) ----
    const int stride = GRID * TPB;
    for (int i4 = blockIdx.x * TPB + threadIdx.x; i4 < NP4; i4 += stride) {
        int b   = i4 >> 17;            // batch (HW4 = 2^17)
        int rem = i4 - (b << 17);
        const float4* base =
            reinterpret_cast<const float4*>(logits + (size_t)b * NC * HW) + rem;

        float4 m = __ldcs(base);
        int ix = 0, iy = 0, iz = 0, iw = 0;
        #pragma unroll
        for (int c = 1; c < NC; c++) {
            float4 v = __ldcs(base + (size_t)c * HW4);
            if (v.x > m.x) { m.x = v.x; ix = c; }
            if (v.y > m.y) { m.y = v.y; iy = c; }
            if (v.z > m.z) { m.z = v.z; iz = c; }
            if (v.w > m.w) { m.w = v.w; iw = c; }
        }

        // target is int32 (JAX x64 disabled => int64 request yields int32)
        int4 t = __ldcs(reinterpret_cast<const int4*>(target) + i4);

        atomicAdd(&sh[t.x * NC + ix], 1u);
        atomicAdd(&sh[t.y * NC + iy], 1u);
        atomicAdd(&sh[t.z * NC + iz], 1u);
        atomicAdd(&sh[t.w * NC + iw], 1u);
    }

    __syncthreads();
    for (int i = threadIdx.x; i < BINS; i += TPB) {
        unsigned int v = sh[i];
        if (v) atomicAdd(&g_cm[i], v);
    }

    // ---- phase 2: last block finalizes ----
    __threadfence();
    __shared__ bool is_last;
    if (threadIdx.x == 0) {
        unsigned int n = atomicAdd(&g_done, 1u);
        is_last = (n == GRID - 1);
    }
    __syncthreads();
    if (!is_last) return;

    __threadfence();  // ensure all blocks' g_cm atomics are visible

    if (threadIdx.x < 32) {
        int lane = threadIdx.x;
        double acc = 0.0;
        if (lane < NC) {
            double rowsum = 0.0, colsum = 0.0;
            #pragma unroll
            for (int j = 0; j < NC; j++) {
                rowsum += (double)g_cm[lane * NC + j];   // axis=1 (pred)
                colsum += (double)g_cm[j * NC + lane];   // axis=0 (true)
            }
            double tp = (double)g_cm[lane * NC + lane];
            double fp = rowsum - tp;
            double fn = colsum - tp;
            double tn = (double)NPIX - tp - fp - fn;     // sum(CM) is exact
            double sens = (tp + SMOOTH) / (tp + fn + SMOOTH);
            double spec = (tn + SMOOTH) / (tn + fp + SMOOTH);
            acc = WEIGHT * sens + (1.0 - WEIGHT) * spec;
        }
        #pragma unroll
        for (int off = 16; off > 0; off >>= 1)
            acc += __shfl_down_sync(0xFFFFFFFFu, acc, off);
        if (lane == 0)
            out[0] = (float)(1.0 - acc / (double)NC);
    }
    __syncthreads();

    // reset globals so the next graph replay starts clean (deterministic)
    for (int i = threadIdx.x; i < BINS; i += TPB) g_cm[i] = 0u;
    if (threadIdx.x == 0) g_done = 0u;
}

extern "C" void kernel_launch(void* const* d_in, const int* in_sizes, int n_in,
                              void* d_out, int out_size) {
    const float* logits = (const float*)d_in[0];
    const int*   target = (const int*)d_in[1];
    float* out = (float*)d_out;

    sensspec_fused_kernel<<<GRID, TPB>>>(logits, target, out);
}